// round 9
// baseline (speedup 1.0000x reference)
#include <cuda_runtime.h>

#define B 4
#define V 20000
#define D 64
#define R 64
#define E 640000
#define BD 256            // B*D
#define LN_EPS 1e-5f

#define NV 8              // vertices per chunk
#define NCHUNK (V / NV)   // 2500
#define GRID_MAIN 296     // 2 blocks per SM
#define NBS 80            // scan blocks (80*256 >= V)
#define ECAP 768          // staged edges per chunk

// Scratch (device globals — zero-initialized at module load; k_main re-zeros
// g_counts behind itself every launch, so hist always starts from zeros)
__device__ float g_relation[R * BD];   // relation[r][b*D+d]
__device__ int   g_counts[V];
__device__ int   g_starts[V];
__device__ int   g_cursor[V];
__device__ int   g_chunk;              // dynamic scheduler ticket (reset in k_scan)
__device__ int   g_edata[E];           // (etype<<16) | src, grouped by dst

// ---------------------------------------------------------------------------
// K1: histogram of destination vertices + relation GEMV (first 16384 threads)
__global__ void k_hist_rel(const int* __restrict__ ei,
                           const float* __restrict__ z,
                           const float* __restrict__ Wz,
                           const float* __restrict__ bz) {
    int i = blockIdx.x * blockDim.x + threadIdx.x;
    if (i < E) atomicAdd(&g_counts[ei[3 * i + 2]], 1);
    if (i < R * BD) {
        int r  = i >> 8;
        int bd = i & 255;
        int b  = bd >> 6;
        int d  = bd & 63;
        int row = r * D + d;
        const float* wrow = Wz + row * D;
        const float* zb   = z + b * D;
        float s = __ldg(&bz[row]);
#pragma unroll
        for (int k = 0; k < D; k++) s = fmaf(__ldg(zb + k), __ldg(wrow + k), s);
        g_relation[i] = s;
    }
}

// K2: single-pass scan. Block bid sums ALL counts below bid*256 (coalesced,
// no cross-block handoff), adds its local inclusive scan, writes exclusive
// starts + cursor. Also resets the k_main scheduler ticket.
__global__ void k_scan() {
    __shared__ int sc[256];
    __shared__ int sRed[8];
    int t = threadIdx.x;
    int bid = blockIdx.x;
    int lane = t & 31;
    int w = t >> 5;
    if (bid == 0 && t == 0) g_chunk = 0;

    // prefix of all blocks below: strided coalesced sum
    int base = bid * 256;
    int s = 0;
    for (int j = t; j < base; j += 256) s += g_counts[j];
#pragma unroll
    for (int o = 16; o >= 1; o >>= 1) s += __shfl_xor_sync(0xffffffffu, s, o);
    if (lane == 0) sRed[w] = s;

    // local inclusive scan of this block's 256 counts
    int i = base + t;
    int c = (i < V) ? g_counts[i] : 0;
    sc[t] = c;
    __syncthreads();
    int pref = sRed[0] + sRed[1] + sRed[2] + sRed[3] +
               sRed[4] + sRed[5] + sRed[6] + sRed[7];
    for (int o = 1; o < 256; o <<= 1) {
        int a = (t >= o) ? sc[t - o] : 0;
        __syncthreads();
        sc[t] += a;
        __syncthreads();
    }
    if (i < V) {
        int st = pref + sc[t] - c;   // global exclusive
        g_starts[i] = st;
        g_cursor[i] = st;
    }
}

// K4: scatter edges into CSR buckets (packed src|etype) — 1 edge/thread
__global__ void k_scatter(const int* __restrict__ ei) {
    int e = blockIdx.x * blockDim.x + threadIdx.x;
    if (e < E) {
        int src = ei[3 * e];
        int et  = ei[3 * e + 1];
        int dst = ei[3 * e + 2];
        int pos = atomicAdd(&g_cursor[dst], 1);
        g_edata[pos] = (et << 16) | src;
    }
}

// ---------------------------------------------------------------------------
// K5: fused aggregation + beta-residual + MLP + LayerNorm + skip.
// Dynamic chunk scheduling via g_chunk ticket.
// Gather: warp w -> b = w&3, half = w>>2; lane covers d-pair via float2 LDG.64.
// Epilogue: thread t = b*64 + d.  Also re-zeros g_counts for the next launch.
__global__ __launch_bounds__(256, 2) void k_main(
    const float* __restrict__ x,
    const float* __restrict__ W1, const float* __restrict__ b1,
    const float* __restrict__ W2, const float* __restrict__ b2,
    const float* __restrict__ beta,
    const float* __restrict__ lnw, const float* __restrict__ lnb,
    float* __restrict__ out) {

    extern __shared__ float smem[];
    float* sRel = smem;                        // R*BD    = 16384 floats
    float* sW1T = sRel + R * BD;               // 4096
    float* sW2T = sW1T + 64 * 64;              // 4096
    float* sH   = sW2T + 64 * 64;              // BD*NV   = 2048
    int*   sE   = (int*)(sH + BD * NV);        // ECAP ints
    __shared__ float sRS[NV][8];
    __shared__ float sRQ[NV][8];
    __shared__ int sVst[NV + 1];               // chunk's start offsets
    __shared__ int sChunk;

    int t = threadIdx.x;
    int w = t >> 5;
    int lane = t & 31;

    // epilogue identity
    int b = t >> 6;
    int d = t & 63;

    // gather identity
    int gb    = w & 3;
    int ghalf = w >> 2;

    // stage relation table and transposed weights (once per block)
    for (int i = t; i < R * BD; i += 256) sRel[i] = g_relation[i];
    for (int i = t; i < 64 * 64; i += 256) {
        int k = i >> 6, dd = i & 63;
        sW1T[i] = __ldg(&W1[dd * 64 + k]);
        sW2T[i] = __ldg(&W2[dd * 64 + k]);
    }

    float bb1 = __ldg(b1 + d), bb2 = __ldg(b2 + d);
    float wln = __ldg(lnw + d), bln = __ldg(lnb + d);
    float2 bet2 = ((const float2*)beta)[lane];

    const float2* xb2 = (const float2*)x + (size_t)gb * (V * D / 2) + lane;
    const float*  xres = x + (size_t)b * V * D + d;
    float* sRelB = sRel + (gb << 6) + 2 * lane;

    for (;;) {
        if (t == 0) sChunk = atomicAdd(&g_chunk, 1);
        __syncthreads();               // publishes sChunk; sE/sH safe to overwrite
        int chunk = sChunk;
        if (chunk >= NCHUNK) break;

        int v0 = chunk * NV;
        // stage this chunk's start offsets (9 values) alongside edge staging
        if (t <= NV) {
            int vv = v0 + t;
            sVst[t] = (vv < V) ? __ldg(&g_starts[vv]) : E;
        }
        if (t >= 32 && t < 32 + NV) g_counts[v0 + t - 32] = 0;  // re-zero
        __syncthreads();
        int eBeg = sVst[0];
        int nE = sVst[NV] - eBeg;

        int nStage = nE < ECAP ? nE : ECAP;
        for (int i = t; i < nStage; i += 256) sE[i] = __ldg(&g_edata[eBeg + i]);
        __syncthreads();

        // ---- gather: each warp handles 4 vertices for its b ----
        for (int q = 0; q < 4; q++) {
            int vi = (ghalf << 2) + q;
            int v  = v0 + vi;
            int lo  = sVst[vi] - eBeg;
            int hi  = sVst[vi + 1] - eBeg;
            int cnt = hi - lo;
            float2 xs2 = __ldg(xb2 + (size_t)v * 32);   // prefetch self term
            float acc0 = 0.f, acc1 = 0.f;

            if (hi <= ECAP) {
                const int* ed = sE + lo;
                int j = 0;
                for (; j + 8 <= cnt; j += 8) {
                    int e0 = ed[j],     e1 = ed[j + 1], e2 = ed[j + 2], e3 = ed[j + 3];
                    int e4 = ed[j + 4], e5 = ed[j + 5], e6 = ed[j + 6], e7 = ed[j + 7];
                    float2 x0 = __ldg(xb2 + (e0 & 0xFFFF) * 32);
                    float2 x1 = __ldg(xb2 + (e1 & 0xFFFF) * 32);
                    float2 x2 = __ldg(xb2 + (e2 & 0xFFFF) * 32);
                    float2 x3 = __ldg(xb2 + (e3 & 0xFFFF) * 32);
                    float2 x4 = __ldg(xb2 + (e4 & 0xFFFF) * 32);
                    float2 x5 = __ldg(xb2 + (e5 & 0xFFFF) * 32);
                    float2 x6 = __ldg(xb2 + (e6 & 0xFFFF) * 32);
                    float2 x7 = __ldg(xb2 + (e7 & 0xFFFF) * 32);
                    float2 r0 = *(const float2*)(sRelB + ((e0 >> 16) << 8));
                    float2 r1 = *(const float2*)(sRelB + ((e1 >> 16) << 8));
                    float2 r2 = *(const float2*)(sRelB + ((e2 >> 16) << 8));
                    float2 r3 = *(const float2*)(sRelB + ((e3 >> 16) << 8));
                    float2 r4 = *(const float2*)(sRelB + ((e4 >> 16) << 8));
                    float2 r5 = *(const float2*)(sRelB + ((e5 >> 16) << 8));
                    float2 r6 = *(const float2*)(sRelB + ((e6 >> 16) << 8));
                    float2 r7 = *(const float2*)(sRelB + ((e7 >> 16) << 8));
                    acc0 = fmaf(r0.x, x0.x, acc0); acc1 = fmaf(r0.y, x0.y, acc1);
                    acc0 = fmaf(r1.x, x1.x, acc0); acc1 = fmaf(r1.y, x1.y, acc1);
                    acc0 = fmaf(r2.x, x2.x, acc0); acc1 = fmaf(r2.y, x2.y, acc1);
                    acc0 = fmaf(r3.x, x3.x, acc0); acc1 = fmaf(r3.y, x3.y, acc1);
                    acc0 = fmaf(r4.x, x4.x, acc0); acc1 = fmaf(r4.y, x4.y, acc1);
                    acc0 = fmaf(r5.x, x5.x, acc0); acc1 = fmaf(r5.y, x5.y, acc1);
                    acc0 = fmaf(r6.x, x6.x, acc0); acc1 = fmaf(r6.y, x6.y, acc1);
                    acc0 = fmaf(r7.x, x7.x, acc0); acc1 = fmaf(r7.y, x7.y, acc1);
                }
                for (; j < cnt; j++) {
                    int e = ed[j];
                    float2 xv = __ldg(xb2 + (e & 0xFFFF) * 32);
                    float2 rv = *(const float2*)(sRelB + ((e >> 16) << 8));
                    acc0 = fmaf(rv.x, xv.x, acc0);
                    acc1 = fmaf(rv.y, xv.y, acc1);
                }
            } else {
                // rare fallback: chunk overflowed staging buffer
                const int* ed = g_edata + eBeg + lo;
                for (int j = 0; j < cnt; j++) {
                    int e = __ldg(ed + j);
                    float2 xv = __ldg(xb2 + (e & 0xFFFF) * 32);
                    float2 rv = *(const float2*)(sRelB + ((e >> 16) << 8));
                    acc0 = fmaf(rv.x, xv.x, acc0);
                    acc1 = fmaf(rv.y, xv.y, acc1);
                }
            }

            int base = ((gb << 6) + 2 * lane) * NV + vi;
            sH[base]      = fmaf(bet2.x, xs2.x, acc0);
            sH[base + NV] = fmaf(bet2.y, xs2.y, acc1);
        }
        __syncthreads();

        // ---- matmul 1: s[vi] = relu(h0[vi] @ W1^T + b1) ----
        float s[NV];
#pragma unroll
        for (int vi = 0; vi < NV; vi++) s[vi] = bb1;
#pragma unroll
        for (int k = 0; k < 64; k++) {
            float wv = sW1T[(k << 6) + d];
            const float4* hp = reinterpret_cast<const float4*>(&sH[((b << 6) + k) * NV]);
            float4 h0 = hp[0], h1 = hp[1];
            s[0] = fmaf(h0.x, wv, s[0]); s[1] = fmaf(h0.y, wv, s[1]);
            s[2] = fmaf(h0.z, wv, s[2]); s[3] = fmaf(h0.w, wv, s[3]);
            s[4] = fmaf(h1.x, wv, s[4]); s[5] = fmaf(h1.y, wv, s[5]);
            s[6] = fmaf(h1.z, wv, s[6]); s[7] = fmaf(h1.w, wv, s[7]);
        }
        __syncthreads();
#pragma unroll
        for (int vi = 0; vi < NV; vi++)
            sH[((b << 6) + d) * NV + vi] = fmaxf(s[vi], 0.f);
        __syncthreads();

        // ---- matmul 2: s[vi] = t1[vi] @ W2^T + b2 ----
#pragma unroll
        for (int vi = 0; vi < NV; vi++) s[vi] = bb2;
#pragma unroll
        for (int k = 0; k < 64; k++) {
            float wv = sW2T[(k << 6) + d];
            const float4* hp = reinterpret_cast<const float4*>(&sH[((b << 6) + k) * NV]);
            float4 h0 = hp[0], h1 = hp[1];
            s[0] = fmaf(h0.x, wv, s[0]); s[1] = fmaf(h0.y, wv, s[1]);
            s[2] = fmaf(h0.z, wv, s[2]); s[3] = fmaf(h0.w, wv, s[3]);
            s[4] = fmaf(h1.x, wv, s[4]); s[5] = fmaf(h1.y, wv, s[5]);
            s[6] = fmaf(h1.z, wv, s[6]); s[7] = fmaf(h1.w, wv, s[7]);
        }

        // ---- LayerNorm (two-pass, warp shuffles + cross-warp combine) ----
        float mu[NV];
#pragma unroll
        for (int vi = 0; vi < NV; vi++) {
            float sm = s[vi];
#pragma unroll
            for (int o = 16; o >= 1; o >>= 1)
                sm += __shfl_xor_sync(0xffffffffu, sm, o);
            if (lane == 0) sRS[vi][w] = sm;
        }
        __syncthreads();
#pragma unroll
        for (int vi = 0; vi < NV; vi++)
            mu[vi] = (sRS[vi][w] + sRS[vi][w ^ 1]) * (1.f / 64.f);
#pragma unroll
        for (int vi = 0; vi < NV; vi++) {
            float hm = s[vi] - mu[vi];
            float q = hm * hm;
#pragma unroll
            for (int o = 16; o >= 1; o >>= 1)
                q += __shfl_xor_sync(0xffffffffu, q, o);
            if (lane == 0) sRQ[vi][w] = q;
        }
        __syncthreads();

        size_t obase = (size_t)b * V * D + (size_t)v0 * D + d;
#pragma unroll
        for (int vi = 0; vi < NV; vi++) {
            float var = (sRQ[vi][w] + sRQ[vi][w ^ 1]) * (1.f / 64.f);
            float hm  = s[vi] - mu[vi];
            float xself = __ldg(xres + (size_t)(v0 + vi) * D);
            out[obase + (size_t)vi * D] =
                fmaf(hm * rsqrtf(var + LN_EPS), wln, bln) + xself;
        }
    }
}

// ---------------------------------------------------------------------------
extern "C" void kernel_launch(void* const* d_in, const int* in_sizes, int n_in,
                              void* d_out, int out_size) {
    const float* x    = (const float*)d_in[0];
    const float* z    = (const float*)d_in[1];
    const int*   ei   = (const int*)d_in[2];
    // d_in[3] = r_index (unused by the reference)
    const float* Wz   = (const float*)d_in[4];
    const float* bz   = (const float*)d_in[5];
    const float* W1   = (const float*)d_in[6];
    const float* b1   = (const float*)d_in[7];
    const float* W2   = (const float*)d_in[8];
    const float* b2   = (const float*)d_in[9];
    const float* beta = (const float*)d_in[10];
    const float* lnw  = (const float*)d_in[11];
    const float* lnb  = (const float*)d_in[12];
    float* out = (float*)d_out;

    const int SMEM_MAIN = (R * BD + 64 * 64 * 2 + BD * NV) * 4 + ECAP * 4; // 109568 B
    cudaFuncSetAttribute(k_main, cudaFuncAttributeMaxDynamicSharedMemorySize,
                         SMEM_MAIN);

    k_hist_rel<<<(E + 255) / 256, 256>>>(ei, z, Wz, bz);
    k_scan<<<NBS, 256>>>();
    k_scatter<<<(E + 255) / 256, 256>>>(ei);
    k_main<<<GRID_MAIN, 256, SMEM_MAIN>>>(x, W1, b1, W2, b2, beta, lnw, lnb, out);
}

// round 10
// speedup vs baseline: 1.4457x; 1.4457x over previous
#include <cuda_runtime.h>

#define B 4
#define V 20000
#define D 64
#define R 64
#define E 640000
#define BD 256            // B*D
#define LN_EPS 1e-5f

#define NV 8              // vertices per chunk
#define NCHUNK (V / NV)   // 2500
#define GRID_MAIN 296     // 2 blocks per SM
#define NBS 80            // scan blocks (80*256 >= V)
#define ECAP 768          // staged edges per chunk

// Scratch (device globals — zero-initialized at module load; k_main re-zeros
// g_counts behind itself every launch, so hist always starts from zeros)
__device__ float g_relation[R * BD];   // relation[r][b*D+d]
__device__ int   g_counts[V];
__device__ int   g_starts[V];
__device__ int   g_cursor[V];
__device__ int   g_chunk;              // dynamic scheduler ticket (reset in k_scan)
__device__ int   g_edata[E];           // (etype<<16) | src, grouped by dst

// ---------------------------------------------------------------------------
// K1: histogram of destination vertices + relation GEMV (first 16384 threads)
__global__ void k_hist_rel(const int* __restrict__ ei,
                           const float* __restrict__ z,
                           const float* __restrict__ Wz,
                           const float* __restrict__ bz) {
    int i = blockIdx.x * blockDim.x + threadIdx.x;
    if (i < E) atomicAdd(&g_counts[ei[3 * i + 2]], 1);
    if (i < R * BD) {
        int r  = i >> 8;
        int bd = i & 255;
        int b  = bd >> 6;
        int d  = bd & 63;
        int row = r * D + d;
        const float* wrow = Wz + row * D;
        const float* zb   = z + b * D;
        float s = __ldg(&bz[row]);
#pragma unroll
        for (int k = 0; k < D; k++) s = fmaf(__ldg(zb + k), __ldg(wrow + k), s);
        g_relation[i] = s;
    }
}

// K2: single-pass scan. Block bid sums ALL counts below bid*256 (coalesced,
// no cross-block handoff), adds its local inclusive scan, writes exclusive
// starts + cursor. Also resets the k_main scheduler ticket.
__global__ void k_scan() {
    __shared__ int sc[256];
    __shared__ int sRed[8];
    int t = threadIdx.x;
    int bid = blockIdx.x;
    int lane = t & 31;
    int w = t >> 5;
    if (bid == 0 && t == 0) g_chunk = 0;

    // prefix of all blocks below: strided coalesced sum
    int base = bid * 256;
    int s = 0;
    for (int j = t; j < base; j += 256) s += g_counts[j];
#pragma unroll
    for (int o = 16; o >= 1; o >>= 1) s += __shfl_xor_sync(0xffffffffu, s, o);
    if (lane == 0) sRed[w] = s;

    // local inclusive scan of this block's 256 counts
    int i = base + t;
    int c = (i < V) ? g_counts[i] : 0;
    sc[t] = c;
    __syncthreads();
    int pref = sRed[0] + sRed[1] + sRed[2] + sRed[3] +
               sRed[4] + sRed[5] + sRed[6] + sRed[7];
    for (int o = 1; o < 256; o <<= 1) {
        int a = (t >= o) ? sc[t - o] : 0;
        __syncthreads();
        sc[t] += a;
        __syncthreads();
    }
    if (i < V) {
        int st = pref + sc[t] - c;   // global exclusive
        g_starts[i] = st;
        g_cursor[i] = st;
    }
}

// K4: scatter edges into CSR buckets (packed src|etype) — 1 edge/thread
__global__ void k_scatter(const int* __restrict__ ei) {
    int e = blockIdx.x * blockDim.x + threadIdx.x;
    if (e < E) {
        int src = ei[3 * e];
        int et  = ei[3 * e + 1];
        int dst = ei[3 * e + 2];
        int pos = atomicAdd(&g_cursor[dst], 1);
        g_edata[pos] = (et << 16) | src;
    }
}

// ---------------------------------------------------------------------------
// K5: fused aggregation + beta-residual + MLP + LayerNorm + skip.
// Dynamic chunk scheduling via g_chunk ticket (load balance).
// Gather: warp w -> b = w&3, half = w>>2; lane covers d-pair via float2 LDG.64.
// Epilogue: thread t = b*64 + d.  Also re-zeros g_counts for the next launch.
// NOTE: gather-loop codegen is fragile (R8 post-mortem) — keep bounds as
// uniform __ldg and keep the self-term load AFTER the edge loop.
__global__ __launch_bounds__(256, 2) void k_main(
    const float* __restrict__ x,
    const float* __restrict__ W1, const float* __restrict__ b1,
    const float* __restrict__ W2, const float* __restrict__ b2,
    const float* __restrict__ beta,
    const float* __restrict__ lnw, const float* __restrict__ lnb,
    float* __restrict__ out) {

    extern __shared__ float smem[];
    float* sRel = smem;                        // R*BD    = 16384 floats
    float* sW1T = sRel + R * BD;               // 4096
    float* sW2T = sW1T + 64 * 64;              // 4096
    float* sH   = sW2T + 64 * 64;              // BD*NV   = 2048
    int*   sE   = (int*)(sH + BD * NV);        // ECAP ints
    __shared__ float sRS[NV][8];
    __shared__ float sRQ[NV][8];
    __shared__ int sChunk;

    int t = threadIdx.x;
    int w = t >> 5;
    int lane = t & 31;

    // epilogue identity
    int b = t >> 6;
    int d = t & 63;

    // gather identity
    int gb    = w & 3;
    int ghalf = w >> 2;

    // stage relation table and transposed weights (once per block)
    for (int i = t; i < R * BD; i += 256) sRel[i] = g_relation[i];
    for (int i = t; i < 64 * 64; i += 256) {
        int k = i >> 6, dd = i & 63;
        sW1T[i] = __ldg(&W1[dd * 64 + k]);
        sW2T[i] = __ldg(&W2[dd * 64 + k]);
    }

    float bb1 = __ldg(b1 + d), bb2 = __ldg(b2 + d);
    float wln = __ldg(lnw + d), bln = __ldg(lnb + d);
    float2 bet2 = ((const float2*)beta)[lane];

    const float2* xb2 = (const float2*)x + (size_t)gb * (V * D / 2) + lane;
    const float*  xres = x + (size_t)b * V * D + d;
    float* sRelB = sRel + (gb << 6) + 2 * lane;

    for (;;) {
        if (t == 0) sChunk = atomicAdd(&g_chunk, 1);
        __syncthreads();               // publishes sChunk; sE/sH safe to overwrite
        int chunk = sChunk;
        if (chunk >= NCHUNK) break;

        int v0 = chunk * NV;
        int eBeg = __ldg(&g_starts[v0]);
        int eEnd = (v0 + NV < V) ? __ldg(&g_starts[v0 + NV]) : E;
        int nE = eEnd - eBeg;

        int nStage = nE < ECAP ? nE : ECAP;
        for (int i = t; i < nStage; i += 256) sE[i] = __ldg(&g_edata[eBeg + i]);
        if (t < NV) g_counts[v0 + t] = 0;     // re-zero for next launch
        __syncthreads();

        // ---- gather: each warp handles 4 vertices for its b ----
        for (int q = 0; q < 4; q++) {
            int vi = (ghalf << 2) + q;
            int v  = v0 + vi;
            int lo  = __ldg(&g_starts[v]) - eBeg;
            int hi  = ((v + 1 < V) ? __ldg(&g_starts[v + 1]) : E) - eBeg;
            int cnt = hi - lo;
            float acc0 = 0.f, acc1 = 0.f;

            if (hi <= ECAP) {
                const int* ed = sE + lo;
                int j = 0;
                for (; j + 8 <= cnt; j += 8) {
                    int e0 = ed[j],     e1 = ed[j + 1], e2 = ed[j + 2], e3 = ed[j + 3];
                    int e4 = ed[j + 4], e5 = ed[j + 5], e6 = ed[j + 6], e7 = ed[j + 7];
                    float2 x0 = __ldg(xb2 + (e0 & 0xFFFF) * 32);
                    float2 x1 = __ldg(xb2 + (e1 & 0xFFFF) * 32);
                    float2 x2 = __ldg(xb2 + (e2 & 0xFFFF) * 32);
                    float2 x3 = __ldg(xb2 + (e3 & 0xFFFF) * 32);
                    float2 x4 = __ldg(xb2 + (e4 & 0xFFFF) * 32);
                    float2 x5 = __ldg(xb2 + (e5 & 0xFFFF) * 32);
                    float2 x6 = __ldg(xb2 + (e6 & 0xFFFF) * 32);
                    float2 x7 = __ldg(xb2 + (e7 & 0xFFFF) * 32);
                    float2 r0 = *(const float2*)(sRelB + ((e0 >> 16) << 8));
                    float2 r1 = *(const float2*)(sRelB + ((e1 >> 16) << 8));
                    float2 r2 = *(const float2*)(sRelB + ((e2 >> 16) << 8));
                    float2 r3 = *(const float2*)(sRelB + ((e3 >> 16) << 8));
                    float2 r4 = *(const float2*)(sRelB + ((e4 >> 16) << 8));
                    float2 r5 = *(const float2*)(sRelB + ((e5 >> 16) << 8));
                    float2 r6 = *(const float2*)(sRelB + ((e6 >> 16) << 8));
                    float2 r7 = *(const float2*)(sRelB + ((e7 >> 16) << 8));
                    acc0 = fmaf(r0.x, x0.x, acc0); acc1 = fmaf(r0.y, x0.y, acc1);
                    acc0 = fmaf(r1.x, x1.x, acc0); acc1 = fmaf(r1.y, x1.y, acc1);
                    acc0 = fmaf(r2.x, x2.x, acc0); acc1 = fmaf(r2.y, x2.y, acc1);
                    acc0 = fmaf(r3.x, x3.x, acc0); acc1 = fmaf(r3.y, x3.y, acc1);
                    acc0 = fmaf(r4.x, x4.x, acc0); acc1 = fmaf(r4.y, x4.y, acc1);
                    acc0 = fmaf(r5.x, x5.x, acc0); acc1 = fmaf(r5.y, x5.y, acc1);
                    acc0 = fmaf(r6.x, x6.x, acc0); acc1 = fmaf(r6.y, x6.y, acc1);
                    acc0 = fmaf(r7.x, x7.x, acc0); acc1 = fmaf(r7.y, x7.y, acc1);
                }
                for (; j < cnt; j++) {
                    int e = ed[j];
                    float2 xv = __ldg(xb2 + (e & 0xFFFF) * 32);
                    float2 rv = *(const float2*)(sRelB + ((e >> 16) << 8));
                    acc0 = fmaf(rv.x, xv.x, acc0);
                    acc1 = fmaf(rv.y, xv.y, acc1);
                }
            } else {
                // rare fallback: chunk overflowed staging buffer
                const int* ed = g_edata + eBeg + lo;
                for (int j = 0; j < cnt; j++) {
                    int e = __ldg(ed + j);
                    float2 xv = __ldg(xb2 + (e & 0xFFFF) * 32);
                    float2 rv = *(const float2*)(sRelB + ((e >> 16) << 8));
                    acc0 = fmaf(rv.x, xv.x, acc0);
                    acc1 = fmaf(rv.y, xv.y, acc1);
                }
            }

            float2 xs2 = __ldg(xb2 + (size_t)v * 32);
            int base = ((gb << 6) + 2 * lane) * NV + vi;
            sH[base]      = fmaf(bet2.x, xs2.x, acc0);
            sH[base + NV] = fmaf(bet2.y, xs2.y, acc1);
        }
        __syncthreads();

        // ---- matmul 1: s[vi] = relu(h0[vi] @ W1^T + b1) ----
        float s[NV];
#pragma unroll
        for (int vi = 0; vi < NV; vi++) s[vi] = bb1;
#pragma unroll
        for (int k = 0; k < 64; k++) {
            float wv = sW1T[(k << 6) + d];
            const float4* hp = reinterpret_cast<const float4*>(&sH[((b << 6) + k) * NV]);
            float4 h0 = hp[0], h1 = hp[1];
            s[0] = fmaf(h0.x, wv, s[0]); s[1] = fmaf(h0.y, wv, s[1]);
            s[2] = fmaf(h0.z, wv, s[2]); s[3] = fmaf(h0.w, wv, s[3]);
            s[4] = fmaf(h1.x, wv, s[4]); s[5] = fmaf(h1.y, wv, s[5]);
            s[6] = fmaf(h1.z, wv, s[6]); s[7] = fmaf(h1.w, wv, s[7]);
        }
        __syncthreads();
#pragma unroll
        for (int vi = 0; vi < NV; vi++)
            sH[((b << 6) + d) * NV + vi] = fmaxf(s[vi], 0.f);
        __syncthreads();

        // ---- matmul 2: s[vi] = t1[vi] @ W2^T + b2 ----
#pragma unroll
        for (int vi = 0; vi < NV; vi++) s[vi] = bb2;
#pragma unroll
        for (int k = 0; k < 64; k++) {
            float wv = sW2T[(k << 6) + d];
            const float4* hp = reinterpret_cast<const float4*>(&sH[((b << 6) + k) * NV]);
            float4 h0 = hp[0], h1 = hp[1];
            s[0] = fmaf(h0.x, wv, s[0]); s[1] = fmaf(h0.y, wv, s[1]);
            s[2] = fmaf(h0.z, wv, s[2]); s[3] = fmaf(h0.w, wv, s[3]);
            s[4] = fmaf(h1.x, wv, s[4]); s[5] = fmaf(h1.y, wv, s[5]);
            s[6] = fmaf(h1.z, wv, s[6]); s[7] = fmaf(h1.w, wv, s[7]);
        }

        // ---- LayerNorm (two-pass, warp shuffles + cross-warp combine) ----
        float mu[NV];
#pragma unroll
        for (int vi = 0; vi < NV; vi++) {
            float sm = s[vi];
#pragma unroll
            for (int o = 16; o >= 1; o >>= 1)
                sm += __shfl_xor_sync(0xffffffffu, sm, o);
            if (lane == 0) sRS[vi][w] = sm;
        }
        __syncthreads();
#pragma unroll
        for (int vi = 0; vi < NV; vi++)
            mu[vi] = (sRS[vi][w] + sRS[vi][w ^ 1]) * (1.f / 64.f);
#pragma unroll
        for (int vi = 0; vi < NV; vi++) {
            float hm = s[vi] - mu[vi];
            float q = hm * hm;
#pragma unroll
            for (int o = 16; o >= 1; o >>= 1)
                q += __shfl_xor_sync(0xffffffffu, q, o);
            if (lane == 0) sRQ[vi][w] = q;
        }
        __syncthreads();

        size_t obase = (size_t)b * V * D + (size_t)v0 * D + d;
#pragma unroll
        for (int vi = 0; vi < NV; vi++) {
            float var = (sRQ[vi][w] + sRQ[vi][w ^ 1]) * (1.f / 64.f);
            float hm  = s[vi] - mu[vi];
            float xself = __ldg(xres + (size_t)(v0 + vi) * D);
            out[obase + (size_t)vi * D] =
                fmaf(hm * rsqrtf(var + LN_EPS), wln, bln) + xself;
        }
    }
}

// ---------------------------------------------------------------------------
extern "C" void kernel_launch(void* const* d_in, const int* in_sizes, int n_in,
                              void* d_out, int out_size) {
    const float* x    = (const float*)d_in[0];
    const float* z    = (const float*)d_in[1];
    const int*   ei   = (const int*)d_in[2];
    // d_in[3] = r_index (unused by the reference)
    const float* Wz   = (const float*)d_in[4];
    const float* bz   = (const float*)d_in[5];
    const float* W1   = (const float*)d_in[6];
    const float* b1   = (const float*)d_in[7];
    const float* W2   = (const float*)d_in[8];
    const float* b2   = (const float*)d_in[9];
    const float* beta = (const float*)d_in[10];
    const float* lnw  = (const float*)d_in[11];
    const float* lnb  = (const float*)d_in[12];
    float* out = (float*)d_out;

    const int SMEM_MAIN = (R * BD + 64 * 64 * 2 + BD * NV) * 4 + ECAP * 4; // 109568 B
    cudaFuncSetAttribute(k_main, cudaFuncAttributeMaxDynamicSharedMemorySize,
                         SMEM_MAIN);

    k_hist_rel<<<(E + 255) / 256, 256>>>(ei, z, Wz, bz);
    k_scan<<<NBS, 256>>>();
    k_scatter<<<(E + 255) / 256, 256>>>(ei);
    k_main<<<GRID_MAIN, 256, SMEM_MAIN>>>(x, W1, b1, W2, b2, beta, lnw, lnb, out);
}

// round 11
// speedup vs baseline: 1.4735x; 1.0193x over previous
#include <cuda_runtime.h>

#define B 4
#define V 20000
#define D 64
#define R 64
#define E 640000
#define BD 256            // B*D
#define LN_EPS 1e-5f

#define NV 8              // vertices per chunk
#define NCHUNK (V / NV)   // 2500
#define GRID_MAIN 444     // 3 blocks per SM (148 SMs), 222 per flavor
#define NBS 80            // scan blocks (80*256 >= V)
#define ECAP 768          // staged edges per chunk

// Scratch (device globals — zero-initialized at module load; k_main re-zeros
// g_counts behind itself every launch, so hist always starts from zeros)
__device__ float g_relation[R * BD];   // relation[r][b*D+d]
__device__ int   g_counts[V];
__device__ int   g_starts[V];
__device__ int   g_cursor[V];
__device__ int   g_chunk2[2];          // per-flavor scheduler tickets
__device__ int   g_edata[E];           // (etype<<16) | src, grouped by dst

// ---------------------------------------------------------------------------
// K1: histogram of destination vertices + relation GEMV (first 16384 threads)
__global__ void k_hist_rel(const int* __restrict__ ei,
                           const float* __restrict__ z,
                           const float* __restrict__ Wz,
                           const float* __restrict__ bz) {
    int i = blockIdx.x * blockDim.x + threadIdx.x;
    if (i < E) atomicAdd(&g_counts[ei[3 * i + 2]], 1);
    if (i < R * BD) {
        int r  = i >> 8;
        int bd = i & 255;
        int b  = bd >> 6;
        int d  = bd & 63;
        int row = r * D + d;
        const float* wrow = Wz + row * D;
        const float* zb   = z + b * D;
        float s = __ldg(&bz[row]);
#pragma unroll
        for (int k = 0; k < D; k++) s = fmaf(__ldg(zb + k), __ldg(wrow + k), s);
        g_relation[i] = s;
    }
}

// K2: single-pass scan. Block bid sums ALL counts below bid*256 (coalesced,
// no cross-block handoff), adds its local inclusive scan, writes exclusive
// starts + cursor. Also resets the k_main scheduler tickets.
__global__ void k_scan() {
    __shared__ int sc[256];
    __shared__ int sRed[8];
    int t = threadIdx.x;
    int bid = blockIdx.x;
    int lane = t & 31;
    int w = t >> 5;
    if (bid == 0 && t < 2) g_chunk2[t] = 0;

    // prefix of all blocks below: strided coalesced sum
    int base = bid * 256;
    int s = 0;
    for (int j = t; j < base; j += 256) s += g_counts[j];
#pragma unroll
    for (int o = 16; o >= 1; o >>= 1) s += __shfl_xor_sync(0xffffffffu, s, o);
    if (lane == 0) sRed[w] = s;

    // local inclusive scan of this block's 256 counts
    int i = base + t;
    int c = (i < V) ? g_counts[i] : 0;
    sc[t] = c;
    __syncthreads();
    int pref = sRed[0] + sRed[1] + sRed[2] + sRed[3] +
               sRed[4] + sRed[5] + sRed[6] + sRed[7];
    for (int o = 1; o < 256; o <<= 1) {
        int a = (t >= o) ? sc[t - o] : 0;
        __syncthreads();
        sc[t] += a;
        __syncthreads();
    }
    if (i < V) {
        int st = pref + sc[t] - c;   // global exclusive
        g_starts[i] = st;
        g_cursor[i] = st;
    }
}

// K4: scatter edges into CSR buckets (packed src|etype) — 1 edge/thread
__global__ void k_scatter(const int* __restrict__ ei) {
    int e = blockIdx.x * blockDim.x + threadIdx.x;
    if (e < E) {
        int src = ei[3 * e];
        int et  = ei[3 * e + 1];
        int dst = ei[3 * e + 2];
        int pos = atomicAdd(&g_cursor[dst], 1);
        g_edata[pos] = (et << 16) | src;
    }
}

// ---------------------------------------------------------------------------
// K5: fused aggregation + beta-residual + MLP + LayerNorm + skip.
// b-pair specialization: flavor = blockIdx&1 handles b in {2f, 2f+1} only ->
// 32KB relation slice -> 3 blocks/SM (24 warps) instead of 2 (16 warps).
// Gather: warp w -> bb = w&1, quarter = w>>1 (2 vertices each); lane covers a
// d-pair via float2 LDG.64. Epilogue: t -> (bb = t>>7, h = (t>>6)&1, d = t&63),
// 4 outputs per thread. NOTE: gather-loop body is codegen-fragile (R8) — keep
// uniform __ldg bounds and self-term load after the edge loop.
__global__ __launch_bounds__(256, 3) void k_main(
    const float* __restrict__ x,
    const float* __restrict__ W1, const float* __restrict__ b1,
    const float* __restrict__ W2, const float* __restrict__ b2,
    const float* __restrict__ beta,
    const float* __restrict__ lnw, const float* __restrict__ lnb,
    float* __restrict__ out) {

    extern __shared__ float smem[];
    float* sRel = smem;                        // R*128   = 8192 floats (32KB)
    float* sW1T = sRel + R * 128;              // 4096
    float* sW2T = sW1T + 64 * 64;              // 4096
    float* sH   = sW2T + 64 * 64;              // 128*NV  = 1024
    int*   sE   = (int*)(sH + 128 * NV);       // ECAP ints
    __shared__ float sRS[NV][8];
    __shared__ float sRQ[NV][8];
    __shared__ int sChunk;

    int t = threadIdx.x;
    int w = t >> 5;
    int lane = t & 31;
    int flavor = blockIdx.x & 1;
    int bBase  = flavor << 1;

    // epilogue identity
    int bb = t >> 7;           // local b (0/1)
    int h  = (t >> 6) & 1;     // vi half (0: vi 0-3, 1: vi 4-7)
    int d  = t & 63;
    int b  = bBase + bb;

    // gather identity
    int gbl     = w & 1;       // local b
    int quarter = w >> 1;      // 0..3, 2 vertices each
    int gb      = bBase + gbl;

    // stage relation slice (columns for this b-pair) and transposed weights
    for (int i = t; i < R * 128; i += 256)
        sRel[i] = g_relation[((i >> 7) << 8) + (bBase << 6) + (i & 127)];
    for (int i = t; i < 64 * 64; i += 256) {
        int k = i >> 6, dd = i & 63;
        sW1T[i] = __ldg(&W1[dd * 64 + k]);
        sW2T[i] = __ldg(&W2[dd * 64 + k]);
    }

    float bb1 = __ldg(b1 + d), bb2 = __ldg(b2 + d);
    float wln = __ldg(lnw + d), bln = __ldg(lnb + d);
    float2 bet2 = ((const float2*)beta)[lane];

    const float2* xb2 = (const float2*)x + (size_t)gb * (V * D / 2) + lane;
    const float*  xres = x + (size_t)b * V * D + d;
    float* sRelB = sRel + (gbl << 6) + 2 * lane;

    for (;;) {
        if (t == 0) sChunk = atomicAdd(&g_chunk2[flavor], 1);
        __syncthreads();               // publishes sChunk; sE/sH safe to overwrite
        int chunk = sChunk;
        if (chunk >= NCHUNK) break;

        int v0 = chunk * NV;
        int eBeg = __ldg(&g_starts[v0]);
        int eEnd = (v0 + NV < V) ? __ldg(&g_starts[v0 + NV]) : E;
        int nE = eEnd - eBeg;

        int nStage = nE < ECAP ? nE : ECAP;
        for (int i = t; i < nStage; i += 256) sE[i] = __ldg(&g_edata[eBeg + i]);
        if (flavor == 0 && t < NV) g_counts[v0 + t] = 0;  // re-zero once
        __syncthreads();

        // ---- gather: each warp handles 2 vertices for its b ----
        for (int q = 0; q < 2; q++) {
            int vi = (quarter << 1) + q;
            int v  = v0 + vi;
            int lo  = __ldg(&g_starts[v]) - eBeg;
            int hi  = ((v + 1 < V) ? __ldg(&g_starts[v + 1]) : E) - eBeg;
            int cnt = hi - lo;
            float acc0 = 0.f, acc1 = 0.f;

            if (hi <= ECAP) {
                const int* ed = sE + lo;
                int j = 0;
                for (; j + 8 <= cnt; j += 8) {
                    int e0 = ed[j],     e1 = ed[j + 1], e2 = ed[j + 2], e3 = ed[j + 3];
                    int e4 = ed[j + 4], e5 = ed[j + 5], e6 = ed[j + 6], e7 = ed[j + 7];
                    float2 x0 = __ldg(xb2 + (e0 & 0xFFFF) * 32);
                    float2 x1 = __ldg(xb2 + (e1 & 0xFFFF) * 32);
                    float2 x2 = __ldg(xb2 + (e2 & 0xFFFF) * 32);
                    float2 x3 = __ldg(xb2 + (e3 & 0xFFFF) * 32);
                    float2 x4 = __ldg(xb2 + (e4 & 0xFFFF) * 32);
                    float2 x5 = __ldg(xb2 + (e5 & 0xFFFF) * 32);
                    float2 x6 = __ldg(xb2 + (e6 & 0xFFFF) * 32);
                    float2 x7 = __ldg(xb2 + (e7 & 0xFFFF) * 32);
                    float2 r0 = *(const float2*)(sRelB + ((e0 >> 16) << 7));
                    float2 r1 = *(const float2*)(sRelB + ((e1 >> 16) << 7));
                    float2 r2 = *(const float2*)(sRelB + ((e2 >> 16) << 7));
                    float2 r3 = *(const float2*)(sRelB + ((e3 >> 16) << 7));
                    float2 r4 = *(const float2*)(sRelB + ((e4 >> 16) << 7));
                    float2 r5 = *(const float2*)(sRelB + ((e5 >> 16) << 7));
                    float2 r6 = *(const float2*)(sRelB + ((e6 >> 16) << 7));
                    float2 r7 = *(const float2*)(sRelB + ((e7 >> 16) << 7));
                    acc0 = fmaf(r0.x, x0.x, acc0); acc1 = fmaf(r0.y, x0.y, acc1);
                    acc0 = fmaf(r1.x, x1.x, acc0); acc1 = fmaf(r1.y, x1.y, acc1);
                    acc0 = fmaf(r2.x, x2.x, acc0); acc1 = fmaf(r2.y, x2.y, acc1);
                    acc0 = fmaf(r3.x, x3.x, acc0); acc1 = fmaf(r3.y, x3.y, acc1);
                    acc0 = fmaf(r4.x, x4.x, acc0); acc1 = fmaf(r4.y, x4.y, acc1);
                    acc0 = fmaf(r5.x, x5.x, acc0); acc1 = fmaf(r5.y, x5.y, acc1);
                    acc0 = fmaf(r6.x, x6.x, acc0); acc1 = fmaf(r6.y, x6.y, acc1);
                    acc0 = fmaf(r7.x, x7.x, acc0); acc1 = fmaf(r7.y, x7.y, acc1);
                }
                for (; j < cnt; j++) {
                    int e = ed[j];
                    float2 xv = __ldg(xb2 + (e & 0xFFFF) * 32);
                    float2 rv = *(const float2*)(sRelB + ((e >> 16) << 7));
                    acc0 = fmaf(rv.x, xv.x, acc0);
                    acc1 = fmaf(rv.y, xv.y, acc1);
                }
            } else {
                // rare fallback: chunk overflowed staging buffer
                const int* ed = g_edata + eBeg + lo;
                for (int j = 0; j < cnt; j++) {
                    int e = __ldg(ed + j);
                    float2 xv = __ldg(xb2 + (e & 0xFFFF) * 32);
                    float2 rv = *(const float2*)(sRelB + ((e >> 16) << 7));
                    acc0 = fmaf(rv.x, xv.x, acc0);
                    acc1 = fmaf(rv.y, xv.y, acc1);
                }
            }

            float2 xs2 = __ldg(xb2 + (size_t)v * 32);
            int base = ((gbl << 6) + 2 * lane) * NV + vi;
            sH[base]      = fmaf(bet2.x, xs2.x, acc0);
            sH[base + NV] = fmaf(bet2.y, xs2.y, acc1);
        }
        __syncthreads();

        // ---- matmul 1: s[j] = relu(h0[h*4+j] @ W1^T + b1) ----
        float s[4];
#pragma unroll
        for (int j = 0; j < 4; j++) s[j] = bb1;
#pragma unroll
        for (int k = 0; k < 64; k++) {
            float wv = sW1T[(k << 6) + d];
            const float4* hp = reinterpret_cast<const float4*>(&sH[((bb << 6) + k) * NV]);
            float4 hv = hp[h];
            s[0] = fmaf(hv.x, wv, s[0]); s[1] = fmaf(hv.y, wv, s[1]);
            s[2] = fmaf(hv.z, wv, s[2]); s[3] = fmaf(hv.w, wv, s[3]);
        }
        __syncthreads();
#pragma unroll
        for (int j = 0; j < 4; j++)
            sH[((bb << 6) + d) * NV + (h << 2) + j] = fmaxf(s[j], 0.f);
        __syncthreads();

        // ---- matmul 2: s[j] = t1[h*4+j] @ W2^T + b2 ----
#pragma unroll
        for (int j = 0; j < 4; j++) s[j] = bb2;
#pragma unroll
        for (int k = 0; k < 64; k++) {
            float wv = sW2T[(k << 6) + d];
            const float4* hp = reinterpret_cast<const float4*>(&sH[((bb << 6) + k) * NV]);
            float4 hv = hp[h];
            s[0] = fmaf(hv.x, wv, s[0]); s[1] = fmaf(hv.y, wv, s[1]);
            s[2] = fmaf(hv.z, wv, s[2]); s[3] = fmaf(hv.w, wv, s[3]);
        }

        // ---- LayerNorm (two-pass, warp shuffles + cross-warp combine) ----
        float mu[4];
#pragma unroll
        for (int j = 0; j < 4; j++) {
            float sm = s[j];
#pragma unroll
            for (int o = 16; o >= 1; o >>= 1)
                sm += __shfl_xor_sync(0xffffffffu, sm, o);
            if (lane == 0) sRS[(h << 2) + j][w] = sm;
        }
        __syncthreads();
#pragma unroll
        for (int j = 0; j < 4; j++)
            mu[j] = (sRS[(h << 2) + j][w] + sRS[(h << 2) + j][w ^ 1]) * (1.f / 64.f);
#pragma unroll
        for (int j = 0; j < 4; j++) {
            float hm = s[j] - mu[j];
            float q = hm * hm;
#pragma unroll
            for (int o = 16; o >= 1; o >>= 1)
                q += __shfl_xor_sync(0xffffffffu, q, o);
            if (lane == 0) sRQ[(h << 2) + j][w] = q;
        }
        __syncthreads();

        size_t obase = (size_t)b * V * D + (size_t)(v0 + (h << 2)) * D + d;
#pragma unroll
        for (int j = 0; j < 4; j++) {
            float var = (sRQ[(h << 2) + j][w] + sRQ[(h << 2) + j][w ^ 1]) * (1.f / 64.f);
            float hm  = s[j] - mu[j];
            float xself = __ldg(xres + (size_t)(v0 + (h << 2) + j) * D);
            out[obase + (size_t)j * D] =
                fmaf(hm * rsqrtf(var + LN_EPS), wln, bln) + xself;
        }
    }
}

// ---------------------------------------------------------------------------
extern "C" void kernel_launch(void* const* d_in, const int* in_sizes, int n_in,
                              void* d_out, int out_size) {
    const float* x    = (const float*)d_in[0];
    const float* z    = (const float*)d_in[1];
    const int*   ei   = (const int*)d_in[2];
    // d_in[3] = r_index (unused by the reference)
    const float* Wz   = (const float*)d_in[4];
    const float* bz   = (const float*)d_in[5];
    const float* W1   = (const float*)d_in[6];
    const float* b1   = (const float*)d_in[7];
    const float* W2   = (const float*)d_in[8];
    const float* b2   = (const float*)d_in[9];
    const float* beta = (const float*)d_in[10];
    const float* lnw  = (const float*)d_in[11];
    const float* lnb  = (const float*)d_in[12];
    float* out = (float*)d_out;

    const int SMEM_MAIN = (R * 128 + 64 * 64 * 2 + 128 * NV) * 4 + ECAP * 4; // 72704 B
    cudaFuncSetAttribute(k_main, cudaFuncAttributeMaxDynamicSharedMemorySize,
                         SMEM_MAIN);

    k_hist_rel<<<(E + 255) / 256, 256>>>(ei, z, Wz, bz);
    k_scan<<<NBS, 256>>>();
    k_scatter<<<(E + 255) / 256, 256>>>(ei);
    k_main<<<GRID_MAIN, 256, SMEM_MAIN>>>(x, W1, b1, W2, b2, beta, lnw, lnb, out);
}

// round 12
// speedup vs baseline: 1.6827x; 1.1420x over previous
#include <cuda_runtime.h>

#define B 4
#define V 20000
#define D 64
#define R 64
#define E 640000
#define BD 256            // B*D
#define LN_EPS 1e-5f

#define NV 8              // vertices per chunk
#define SHST 12           // sH row stride (floats): 8-way instead of 16-way STS conflicts
#define NCHUNK (V / NV)   // 2500
#define GRID_MAIN 592     // 4 blocks per SM (148 SMs), 296 per flavor
#define NBS 80            // scan blocks (80*256 >= V)
#define ECAP 768          // staged edges per chunk

// Scratch (device globals — zero-initialized at module load; k_main re-zeros
// g_counts behind itself every launch, so hist always starts from zeros)
__device__ float g_relation[R * BD];   // relation[r][b*D+d]
__device__ float g_W1T[64 * 64];       // W1 transposed: [k][d]
__device__ float g_W2T[64 * 64];       // W2 transposed: [k][d]
__device__ int   g_counts[V];
__device__ int   g_starts[V];
__device__ int   g_cursor[V];
__device__ int   g_chunk2[2];          // per-flavor scheduler tickets
__device__ int   g_edata[E];           // (etype<<16) | src, grouped by dst

// ---------------------------------------------------------------------------
// K1: histogram + relation GEMV + weight transposes
__global__ void k_hist_rel(const int* __restrict__ ei,
                           const float* __restrict__ z,
                           const float* __restrict__ Wz,
                           const float* __restrict__ bz,
                           const float* __restrict__ W1,
                           const float* __restrict__ W2) {
    int i = blockIdx.x * blockDim.x + threadIdx.x;
    if (i < E) atomicAdd(&g_counts[ei[3 * i + 2]], 1);
    if (i < R * BD) {
        int r  = i >> 8;
        int bd = i & 255;
        int b  = bd >> 6;
        int d  = bd & 63;
        int row = r * D + d;
        const float* wrow = Wz + row * D;
        const float* zb   = z + b * D;
        float s = __ldg(&bz[row]);
#pragma unroll
        for (int k = 0; k < D; k++) s = fmaf(__ldg(zb + k), __ldg(wrow + k), s);
        g_relation[i] = s;
    }
    if (i < 64 * 64) {   // i = k*64 + d
        g_W1T[i] = __ldg(&W1[(i & 63) * 64 + (i >> 6)]);
        g_W2T[i] = __ldg(&W2[(i & 63) * 64 + (i >> 6)]);
    }
}

// K2: single-pass scan. Block bid sums ALL counts below bid*256 (coalesced,
// no cross-block handoff), adds its local inclusive scan, writes exclusive
// starts + cursor. Also resets the k_main scheduler tickets.
__global__ void k_scan() {
    __shared__ int sc[256];
    __shared__ int sRed[8];
    int t = threadIdx.x;
    int bid = blockIdx.x;
    int lane = t & 31;
    int w = t >> 5;
    if (bid == 0 && t < 2) g_chunk2[t] = 0;

    int base = bid * 256;
    int s = 0;
    for (int j = t; j < base; j += 256) s += g_counts[j];
#pragma unroll
    for (int o = 16; o >= 1; o >>= 1) s += __shfl_xor_sync(0xffffffffu, s, o);
    if (lane == 0) sRed[w] = s;

    int i = base + t;
    int c = (i < V) ? g_counts[i] : 0;
    sc[t] = c;
    __syncthreads();
    int pref = sRed[0] + sRed[1] + sRed[2] + sRed[3] +
               sRed[4] + sRed[5] + sRed[6] + sRed[7];
    for (int o = 1; o < 256; o <<= 1) {
        int a = (t >= o) ? sc[t - o] : 0;
        __syncthreads();
        sc[t] += a;
        __syncthreads();
    }
    if (i < V) {
        int st = pref + sc[t] - c;   // global exclusive
        g_starts[i] = st;
        g_cursor[i] = st;
    }
}

// K4: scatter edges into CSR buckets (packed src|etype) — 1 edge/thread
__global__ void k_scatter(const int* __restrict__ ei) {
    int e = blockIdx.x * blockDim.x + threadIdx.x;
    if (e < E) {
        int src = ei[3 * e];
        int et  = ei[3 * e + 1];
        int dst = ei[3 * e + 2];
        int pos = atomicAdd(&g_cursor[dst], 1);
        g_edata[pos] = (et << 16) | src;
    }
}

// ---------------------------------------------------------------------------
// K5: fused aggregation + beta-residual + MLP + LayerNorm + skip.
// b-pair specialization (flavor = blockIdx&1), 4 blocks/SM:
//   smem = 32KB rel slice + 6KB sH + 3KB sE; weights via L1-cached gmem.
// Gather: warp w -> bb = w&1, quarter = w>>1 (2 vertices each); lane = d-pair
// via float2 LDG.64; unroll 4 to fit 64 regs. Epilogue: t -> (bb, h, d),
// 4 outputs per thread. NOTE: gather-loop body is codegen-fragile (R8) — keep
// uniform __ldg bounds and self-term load after the edge loop.
__global__ __launch_bounds__(256, 4) void k_main(
    const float* __restrict__ x,
    const float* __restrict__ b1, const float* __restrict__ b2,
    const float* __restrict__ beta,
    const float* __restrict__ lnw, const float* __restrict__ lnb,
    float* __restrict__ out) {

    extern __shared__ float smem[];
    float* sRel = smem;                        // R*128   = 8192 floats (32KB)
    float* sH   = sRel + R * 128;              // 128*SHST = 1536 floats (6KB)
    int*   sE   = (int*)(sH + 128 * SHST);     // ECAP ints (3KB)
    __shared__ float sRS[NV][8];
    __shared__ float sRQ[NV][8];
    __shared__ int sChunk;

    int t = threadIdx.x;
    int w = t >> 5;
    int lane = t & 31;
    int flavor = blockIdx.x & 1;
    int bBase  = flavor << 1;

    // epilogue identity
    int bb = t >> 7;           // local b (0/1)
    int h  = (t >> 6) & 1;     // vi half (0: vi 0-3, 1: vi 4-7)
    int d  = t & 63;
    int b  = bBase + bb;

    // gather identity
    int gbl     = w & 1;       // local b
    int quarter = w >> 1;      // 0..3, 2 vertices each
    int gb      = bBase + gbl;

    // stage relation slice (columns for this b-pair)
    for (int i = t; i < R * 128; i += 256)
        sRel[i] = g_relation[((i >> 7) << 8) + (bBase << 6) + (i & 127)];

    float bb1 = __ldg(b1 + d), bb2 = __ldg(b2 + d);
    float wln = __ldg(lnw + d), bln = __ldg(lnb + d);
    float2 bet2 = ((const float2*)beta)[lane];

    const float2* xb2 = (const float2*)x + (size_t)gb * (V * D / 2) + lane;
    const float*  xres = x + (size_t)b * V * D + d;
    float* sRelB = sRel + (gbl << 6) + 2 * lane;

    for (;;) {
        if (t == 0) sChunk = atomicAdd(&g_chunk2[flavor], 1);
        __syncthreads();               // publishes sChunk; sE/sH safe to overwrite
        int chunk = sChunk;
        if (chunk >= NCHUNK) break;

        int v0 = chunk * NV;
        int eBeg = __ldg(&g_starts[v0]);
        int eEnd = (v0 + NV < V) ? __ldg(&g_starts[v0 + NV]) : E;
        int nE = eEnd - eBeg;

        int nStage = nE < ECAP ? nE : ECAP;
        for (int i = t; i < nStage; i += 256) sE[i] = __ldg(&g_edata[eBeg + i]);
        if (flavor == 0 && t < NV) g_counts[v0 + t] = 0;  // re-zero once
        __syncthreads();

        // ---- gather: each warp handles 2 vertices for its b ----
        for (int q = 0; q < 2; q++) {
            int vi = (quarter << 1) + q;
            int v  = v0 + vi;
            int lo  = __ldg(&g_starts[v]) - eBeg;
            int hi  = ((v + 1 < V) ? __ldg(&g_starts[v + 1]) : E) - eBeg;
            int cnt = hi - lo;
            float acc0 = 0.f, acc1 = 0.f;

            if (hi <= ECAP) {
                const int* ed = sE + lo;
                int j = 0;
                for (; j + 4 <= cnt; j += 4) {
                    int e0 = ed[j],     e1 = ed[j + 1];
                    int e2 = ed[j + 2], e3 = ed[j + 3];
                    float2 x0 = __ldg(xb2 + (e0 & 0xFFFF) * 32);
                    float2 x1 = __ldg(xb2 + (e1 & 0xFFFF) * 32);
                    float2 x2 = __ldg(xb2 + (e2 & 0xFFFF) * 32);
                    float2 x3 = __ldg(xb2 + (e3 & 0xFFFF) * 32);
                    float2 r0 = *(const float2*)(sRelB + ((e0 >> 16) << 7));
                    float2 r1 = *(const float2*)(sRelB + ((e1 >> 16) << 7));
                    float2 r2 = *(const float2*)(sRelB + ((e2 >> 16) << 7));
                    float2 r3 = *(const float2*)(sRelB + ((e3 >> 16) << 7));
                    acc0 = fmaf(r0.x, x0.x, acc0); acc1 = fmaf(r0.y, x0.y, acc1);
                    acc0 = fmaf(r1.x, x1.x, acc0); acc1 = fmaf(r1.y, x1.y, acc1);
                    acc0 = fmaf(r2.x, x2.x, acc0); acc1 = fmaf(r2.y, x2.y, acc1);
                    acc0 = fmaf(r3.x, x3.x, acc0); acc1 = fmaf(r3.y, x3.y, acc1);
                }
                for (; j < cnt; j++) {
                    int e = ed[j];
                    float2 xv = __ldg(xb2 + (e & 0xFFFF) * 32);
                    float2 rv = *(const float2*)(sRelB + ((e >> 16) << 7));
                    acc0 = fmaf(rv.x, xv.x, acc0);
                    acc1 = fmaf(rv.y, xv.y, acc1);
                }
            } else {
                // rare fallback: chunk overflowed staging buffer
                const int* ed = g_edata + eBeg + lo;
                for (int j = 0; j < cnt; j++) {
                    int e = __ldg(ed + j);
                    float2 xv = __ldg(xb2 + (e & 0xFFFF) * 32);
                    float2 rv = *(const float2*)(sRelB + ((e >> 16) << 7));
                    acc0 = fmaf(rv.x, xv.x, acc0);
                    acc1 = fmaf(rv.y, xv.y, acc1);
                }
            }

            float2 xs2 = __ldg(xb2 + (size_t)v * 32);
            int base = ((gbl << 6) + 2 * lane) * SHST + vi;
            sH[base]        = fmaf(bet2.x, xs2.x, acc0);
            sH[base + SHST] = fmaf(bet2.y, xs2.y, acc1);
        }
        __syncthreads();

        // ---- matmul 1: s[j] = relu(h0[h*4+j] @ W1^T + b1) ----
        float s[4];
#pragma unroll
        for (int j = 0; j < 4; j++) s[j] = bb1;
#pragma unroll
        for (int k = 0; k < 64; k++) {
            float wv = __ldg(&g_W1T[(k << 6) + d]);
            const float4* hp = reinterpret_cast<const float4*>(&sH[((bb << 6) + k) * SHST]);
            float4 hv = hp[h];
            s[0] = fmaf(hv.x, wv, s[0]); s[1] = fmaf(hv.y, wv, s[1]);
            s[2] = fmaf(hv.z, wv, s[2]); s[3] = fmaf(hv.w, wv, s[3]);
        }
        __syncthreads();
        {
            float4* sHrow = reinterpret_cast<float4*>(&sH[((bb << 6) + d) * SHST]);
            sHrow[h] = make_float4(fmaxf(s[0], 0.f), fmaxf(s[1], 0.f),
                                   fmaxf(s[2], 0.f), fmaxf(s[3], 0.f));
        }
        __syncthreads();

        // ---- matmul 2: s[j] = t1[h*4+j] @ W2^T + b2 ----
#pragma unroll
        for (int j = 0; j < 4; j++) s[j] = bb2;
#pragma unroll
        for (int k = 0; k < 64; k++) {
            float wv = __ldg(&g_W2T[(k << 6) + d]);
            const float4* hp = reinterpret_cast<const float4*>(&sH[((bb << 6) + k) * SHST]);
            float4 hv = hp[h];
            s[0] = fmaf(hv.x, wv, s[0]); s[1] = fmaf(hv.y, wv, s[1]);
            s[2] = fmaf(hv.z, wv, s[2]); s[3] = fmaf(hv.w, wv, s[3]);
        }

        // ---- LayerNorm (two-pass, warp shuffles + cross-warp combine) ----
        float mu[4];
#pragma unroll
        for (int j = 0; j < 4; j++) {
            float sm = s[j];
#pragma unroll
            for (int o = 16; o >= 1; o >>= 1)
                sm += __shfl_xor_sync(0xffffffffu, sm, o);
            if (lane == 0) sRS[(h << 2) + j][w] = sm;
        }
        __syncthreads();
#pragma unroll
        for (int j = 0; j < 4; j++)
            mu[j] = (sRS[(h << 2) + j][w] + sRS[(h << 2) + j][w ^ 1]) * (1.f / 64.f);
#pragma unroll
        for (int j = 0; j < 4; j++) {
            float hm = s[j] - mu[j];
            float q = hm * hm;
#pragma unroll
            for (int o = 16; o >= 1; o >>= 1)
                q += __shfl_xor_sync(0xffffffffu, q, o);
            if (lane == 0) sRQ[(h << 2) + j][w] = q;
        }
        __syncthreads();

        size_t obase = (size_t)b * V * D + (size_t)(v0 + (h << 2)) * D + d;
#pragma unroll
        for (int j = 0; j < 4; j++) {
            float var = (sRQ[(h << 2) + j][w] + sRQ[(h << 2) + j][w ^ 1]) * (1.f / 64.f);
            float hm  = s[j] - mu[j];
            float xself = __ldg(xres + (size_t)(v0 + (h << 2) + j) * D);
            out[obase + (size_t)j * D] =
                fmaf(hm * rsqrtf(var + LN_EPS), wln, bln) + xself;
        }
    }
}

// ---------------------------------------------------------------------------
extern "C" void kernel_launch(void* const* d_in, const int* in_sizes, int n_in,
                              void* d_out, int out_size) {
    const float* x    = (const float*)d_in[0];
    const float* z    = (const float*)d_in[1];
    const int*   ei   = (const int*)d_in[2];
    // d_in[3] = r_index (unused by the reference)
    const float* Wz   = (const float*)d_in[4];
    const float* bz   = (const float*)d_in[5];
    const float* W1   = (const float*)d_in[6];
    const float* b1   = (const float*)d_in[7];
    const float* W2   = (const float*)d_in[8];
    const float* b2   = (const float*)d_in[9];
    const float* beta = (const float*)d_in[10];
    const float* lnw  = (const float*)d_in[11];
    const float* lnb  = (const float*)d_in[12];
    float* out = (float*)d_out;

    const int SMEM_MAIN = (R * 128 + 128 * SHST) * 4 + ECAP * 4;  // 41984 B
    cudaFuncSetAttribute(k_main, cudaFuncAttributeMaxDynamicSharedMemorySize,
                         SMEM_MAIN);

    k_hist_rel<<<(E + 255) / 256, 256>>>(ei, z, Wz, bz, W1, W2);
    k_scan<<<NBS, 256>>>();
    k_scatter<<<(E + 255) / 256, 256>>>(ei);
    k_main<<<GRID_MAIN, 256, SMEM_MAIN>>>(x, b1, b2, beta, lnw, lnb, out);
}